// round 17
// baseline (speedup 1.0000x reference)
#include <cuda_runtime.h>
#include <cuda_bf16.h>
#include <math.h>

#define C   64
#define HW  64
#define NSP 4096
#define BB  8
#define EPSBN 1e-5f

// attention tiling
#define TNQ 128           // query rows per CTA (8 warps x 16 rows) -> 2 CTAs/SM
#define TMK 64
#define PK64 68
#define PV64 20

// conv1 mma smem pitches
#define PB1 132
#define PW1 20

#define QSCALE 0.18033688f

// scratch (no allocations allowed -> device globals)
__device__ unsigned long long g_K64[BB * 16 * NSP];
__device__ unsigned long long g_V64[BB * 64 * 64 * 16];
__device__ float g_attn[BB * C * NSP];

// ---------------------------------------------------------------------------
// helpers
// ---------------------------------------------------------------------------
__device__ __forceinline__ unsigned packbf16(float lo, float hi) {
    unsigned r;
    asm("cvt.rn.bf16x2.f32 %0, %1, %2;" : "=r"(r) : "f"(hi), "f"(lo));
    return r;
}
__device__ __forceinline__ unsigned f2tf32(float f) {
    unsigned u;
    asm("cvt.rna.tf32.f32 %0, %1;" : "=r"(u) : "f"(f));
    return u;
}
__device__ __forceinline__ float ex2(float x) {
    float r;
    asm("ex2.approx.ftz.f32 %0, %1;" : "=f"(r) : "f"(x));
    return r;
}
__device__ __forceinline__ void mma_bf16(float c[4],
                                         unsigned a0, unsigned a1, unsigned a2, unsigned a3,
                                         unsigned b0, unsigned b1) {
    asm volatile(
        "mma.sync.aligned.m16n8k16.row.col.f32.bf16.bf16.f32 "
        "{%0,%1,%2,%3},{%4,%5,%6,%7},{%8,%9},{%0,%1,%2,%3};\n"
        : "+f"(c[0]), "+f"(c[1]), "+f"(c[2]), "+f"(c[3])
        : "r"(a0), "r"(a1), "r"(a2), "r"(a3), "r"(b0), "r"(b1));
}
__device__ __forceinline__ void mma_tf32(float c[4],
                                         unsigned a0, unsigned a1, unsigned a2, unsigned a3,
                                         unsigned b0, unsigned b1) {
    asm volatile(
        "mma.sync.aligned.m16n8k8.row.col.f32.tf32.tf32.f32 "
        "{%0,%1,%2,%3},{%4,%5,%6,%7},{%8,%9},{%0,%1,%2,%3};\n"
        : "+f"(c[0]), "+f"(c[1]), "+f"(c[2]), "+f"(c[3])
        : "r"(a0), "r"(a1), "r"(a2), "r"(a3), "r"(b0), "r"(b1));
}
__device__ __forceinline__ void cpa16(unsigned smem_addr, const void* gptr) {
    asm volatile("cp.async.cg.shared.global [%0], [%1], 16;"
                 :: "r"(smem_addr), "l"(gptr));
}

// ---------------------------------------------------------------------------
// conv1 via bf16 mma (R14 verbatim)
// ---------------------------------------------------------------------------
__global__ __launch_bounds__(256) void conv1_mma_kernel(
    const float* __restrict__ x, const float* __restrict__ w1,
    const float* __restrict__ g, const float* __restrict__ bb,
    const float* __restrict__ m, const float* __restrict__ v)
{
    __shared__ __align__(16) unsigned long long Bs[16 * PB1];
    __shared__ __align__(16) unsigned long long Ws[64 * PW1];
    __shared__ float s_inv[C], s_shift[C];

    const int tid  = threadIdx.x;
    const int lane = tid & 31;
    const int wid  = tid >> 5;
    const int gq_g = lane >> 2;
    const int gq_q = lane & 3;

    const int b  = blockIdx.y;
    const int n0 = blockIdx.x * 128;
    const float* xb = x + (size_t)b * C * NSP;

    {
        unsigned long long* kp = g_K64 + (size_t)b * 16 * NSP;
#pragma unroll
        for (int i = 0; i < 8; i++) {
            int idx = tid + i * 256;
            int s = idx >> 7, n = idx & 127;
            int ks = s >> 2, q = s & 3;
            int c0 = 16 * ks + 2 * q;
            float xl0 = xb[(size_t)c0 * NSP + n0 + n];
            float xl1 = xb[(size_t)(c0 + 1) * NSP + n0 + n];
            float xh0 = xb[(size_t)(c0 + 8) * NSP + n0 + n];
            float xh1 = xb[(size_t)(c0 + 9) * NSP + n0 + n];
            unsigned lo = packbf16(xl0, xl1);
            unsigned hi = packbf16(xh0, xh1);
            unsigned long long u = (unsigned long long)lo | ((unsigned long long)hi << 32);
            Bs[s * PB1 + n] = u;
            kp[(size_t)s * NSP + n0 + n] = u;
        }
    }
    {
#pragma unroll
        for (int i = 0; i < 4; i++) {
            int idx = tid + i * 256;
            int r = idx >> 4, s = idx & 15;
            int ks = s >> 2, q = s & 3;
            const float* wr = w1 + r * 64 + 16 * ks + 2 * q;
            float2 wl = *(const float2*)wr;
            float2 wh = *(const float2*)(wr + 8);
            unsigned lo = packbf16(wl.x, wl.y);
            unsigned hi = packbf16(wh.x, wh.y);
            Ws[r * PW1 + s] = (unsigned long long)lo | ((unsigned long long)hi << 32);
        }
    }
    if (tid < C) {
        float inv = g[tid] * rsqrtf(v[tid] + EPSBN);
        s_inv[tid] = inv;
        s_shift[tid] = bb[tid] - m[tid] * inv;
    }
    __syncthreads();

    float OC[4][2][4];
#pragma unroll
    for (int mt = 0; mt < 4; mt++)
#pragma unroll
        for (int nt = 0; nt < 2; nt++)
            OC[mt][nt][0] = OC[mt][nt][1] = OC[mt][nt][2] = OC[mt][nt][3] = 0.f;

    const uint2* Bc = (const uint2*)Bs;
    const uint2* Wc = (const uint2*)Ws;
#pragma unroll
    for (int ks = 0; ks < 4; ks++) {
        int srow = (ks * 4 + gq_q);
        uint2 bf0 = Bc[srow * PB1 + wid * 16 + 0 * 8 + gq_g];
        uint2 bf1 = Bc[srow * PB1 + wid * 16 + 1 * 8 + gq_g];
#pragma unroll
        for (int mt = 0; mt < 4; mt++) {
            uint2 afl = Wc[(mt * 16 + gq_g) * PW1 + srow];
            uint2 afh = Wc[(mt * 16 + gq_g + 8) * PW1 + srow];
            mma_bf16(OC[mt][0], afl.x, afh.x, afl.y, afh.y, bf0.x, bf0.y);
            mma_bf16(OC[mt][1], afl.x, afh.x, afl.y, afh.y, bf1.x, bf1.y);
        }
    }

    {
        unsigned* vp32 = (unsigned*)g_V64;
        int t = (wid & 3) * 4 + gq_q;
        int ch = 2 * blockIdx.x + (wid >> 2);
#pragma unroll
        for (int mt = 0; mt < 4; mt++) {
            int d0 = mt * 16 + gq_g;
            float i0v = s_inv[d0], sh0 = s_shift[d0];
            float i1v = s_inv[d0 + 8], sh1 = s_shift[d0 + 8];
#pragma unroll
            for (int nt = 0; nt < 2; nt++) {
                float v00 = fmaxf(OC[mt][nt][0] * i0v + sh0, 0.f);
                float v01 = fmaxf(OC[mt][nt][1] * i0v + sh0, 0.f);
                float v10 = fmaxf(OC[mt][nt][2] * i1v + sh1, 0.f);
                float v11 = fmaxf(OC[mt][nt][3] * i1v + sh1, 0.f);
                size_t base0 = ((((size_t)b * 64 + d0) * 64 + ch) * 16 + t) * 2 + nt;
                size_t base1 = ((((size_t)b * 64 + d0 + 8) * 64 + ch) * 16 + t) * 2 + nt;
                vp32[base0] = packbf16(v00, v01);
                vp32[base1] = packbf16(v10, v11);
            }
        }
    }
}

// ---------------------------------------------------------------------------
// flash attention: TNQ=128 (16 rows/warp), 2 CTAs/SM.
// PV lags one chunk; V triple-buffered; K double-buffered.
// TWO barriers per chunk: top = data-visibility, bottom = WAR protection
// (ISSUE(mm+1) overwrites K[(mm-1)&1], which S(mm-1) reads -> must complete).
// ---------------------------------------------------------------------------
__global__ __launch_bounds__(256, 2) void attn_mma_kernel(const float* __restrict__ x)
{
    __shared__ __align__(16) unsigned long long Ks64[2][16 * PK64];
    __shared__ __align__(16) unsigned long long Vs64[3][64 * PV64];

    const int tid  = threadIdx.x;
    const int lane = tid & 31;
    const int wid  = tid >> 5;
    const int g    = lane >> 2;
    const int q    = lane & 3;
    const int i0   = wid * 16;

    const int b  = blockIdx.y;
    const int n0 = blockIdx.x * TNQ;
    const float* xb = x + (size_t)b * C * NSP;
    const unsigned long long* kb64 = g_K64 + (size_t)b * 16 * NSP;
    const unsigned long long* vb64 = g_V64 + (size_t)b * 64 * 64 * 16;

    unsigned ksa[2], vsa[3];
    ksa[0] = (unsigned)__cvta_generic_to_shared(&Ks64[0][0]);
    ksa[1] = (unsigned)__cvta_generic_to_shared(&Ks64[1][0]);
    vsa[0] = (unsigned)__cvta_generic_to_shared(&Vs64[0][0]);
    vsa[1] = (unsigned)__cvta_generic_to_shared(&Vs64[1][0]);
    vsa[2] = (unsigned)__cvta_generic_to_shared(&Vs64[2][0]);
    const int i2  = tid * 2;
    const int i2b = i2 + 512;

    // ---- Q A-fragments (16 rows per warp) ----
    unsigned QA[4][4];
#pragma unroll
    for (int ks = 0; ks < 4; ks++) {
        int re = n0 + i0 + g;
        int d0 = 16 * ks + 2 * q;
        QA[ks][0] = packbf16(xb[(size_t)d0 * NSP + re] * QSCALE,
                             xb[(size_t)(d0 + 1) * NSP + re] * QSCALE);
        QA[ks][1] = packbf16(xb[(size_t)d0 * NSP + re + 8] * QSCALE,
                             xb[(size_t)(d0 + 1) * NSP + re + 8] * QSCALE);
        QA[ks][2] = packbf16(xb[(size_t)(d0 + 8) * NSP + re] * QSCALE,
                             xb[(size_t)(d0 + 9) * NSP + re] * QSCALE);
        QA[ks][3] = packbf16(xb[(size_t)(d0 + 8) * NSP + re + 8] * QSCALE,
                             xb[(size_t)(d0 + 9) * NSP + re + 8] * QSCALE);
    }

    float SC[8][4];
    float OC[8][4];
    unsigned PH[8][2];
#pragma unroll
    for (int t = 0; t < 8; t++)
        OC[t][0] = OC[t][1] = OC[t][2] = OC[t][3] = 0.f;
    float rl0 = 0.f, rl1 = 0.f;

    #define ISSUE_CHUNK(m0, kbuf, vbuf) do {                                            \
        int _ch = (m0) >> 6;                                                            \
        cpa16(ksa[kbuf] + ((i2  >> 6) * PK64 + (i2  & 63)) * 8,                         \
              kb64 + (size_t)(i2  >> 6) * NSP + (m0) + (i2  & 63));                     \
        cpa16(ksa[kbuf] + ((i2b >> 6) * PK64 + (i2b & 63)) * 8,                         \
              kb64 + (size_t)(i2b >> 6) * NSP + (m0) + (i2b & 63));                     \
        cpa16(vsa[vbuf] + ((i2  >> 4) * PV64 + (i2  & 15)) * 8,                         \
              vb64 + (size_t)((i2  >> 4) * 64 + _ch) * 16 + (i2  & 15));                \
        cpa16(vsa[vbuf] + ((i2b >> 4) * PV64 + (i2b & 15)) * 8,                         \
              vb64 + (size_t)((i2b >> 4) * 64 + _ch) * 16 + (i2b & 15));                \
        asm volatile("cp.async.commit_group;");                                         \
    } while (0)

    ISSUE_CHUNK(0, 0, 0);

    int vm1 = 2;
    int vnx = 1;

    for (int mm = 0; mm < NSP / TMK; mm++) {
        int kcur = mm & 1;
        if (mm + 1 < NSP / TMK) {
            ISSUE_CHUNK((mm + 1) * TMK, 1 - kcur, vnx);
            asm volatile("cp.async.wait_group 1;");
        } else {
            asm volatile("cp.async.wait_group 0;");
        }
        __syncthreads();              // chunk mm visible to all warps

        const uint2* Kc = (const uint2*)&Ks64[kcur][0];
        const uint2* Vp = (const uint2*)((const unsigned long long*)Vs64 + vm1 * (64 * PV64));

        // ---- S = Q K^T ----
#pragma unroll
        for (int t = 0; t < 8; t++)
            SC[t][0] = SC[t][1] = SC[t][2] = SC[t][3] = 0.f;
#pragma unroll
        for (int ks = 0; ks < 4; ks++) {
            int srow = (ks * 4 + q) * PK64;
#pragma unroll
            for (int nt = 0; nt < 8; nt++) {
                uint2 kf = Kc[srow + nt * 8 + g];
                mma_bf16(SC[nt], QA[ks][0], QA[ks][1], QA[ks][2], QA[ks][3], kf.x, kf.y);
            }
        }

        // ---- per jt: PV(mm-1) (reads PH) THEN exp(mm) overwrites PH ----
#pragma unroll
        for (int jt = 0; jt < 4; jt++) {
            if (mm > 0) {
                unsigned a0 = PH[2 * jt][0],     a1 = PH[2 * jt][1];
                unsigned a2 = PH[2 * jt + 1][0], a3 = PH[2 * jt + 1][1];
#pragma unroll
                for (int nt2 = 0; nt2 < 8; nt2++) {
                    uint2 vf = Vp[(nt2 * 8 + g) * PV64 + jt * 4 + q];
                    mma_bf16(OC[nt2], a0, a1, a2, a3, vf.x, vf.y);
                }
            }
#pragma unroll
            for (int u = 0; u < 2; u++) {
                int nt = 2 * jt + u;
                float e0 = ex2(SC[nt][0]);
                float e1 = ex2(SC[nt][1]);
                float e2 = ex2(SC[nt][2]);
                float e3 = ex2(SC[nt][3]);
                rl0 += e0 + e1;
                rl1 += e2 + e3;
                PH[nt][0] = packbf16(e0, e1);
                PH[nt][1] = packbf16(e2, e3);
            }
        }

        __syncthreads();              // WAR: all reads of K[kcur]/V[vm1] done
        vm1 = (vm1 == 2) ? 0 : vm1 + 1;
        vnx = (vnx == 2) ? 0 : vnx + 1;
    }

    // ---- epilogue: PV of chunk 63 (no pending writes to V[vm1]) ----
    {
        const uint2* Vp = (const uint2*)((const unsigned long long*)Vs64 + vm1 * (64 * PV64));
#pragma unroll
        for (int jt = 0; jt < 4; jt++) {
            unsigned a0 = PH[2 * jt][0],     a1 = PH[2 * jt][1];
            unsigned a2 = PH[2 * jt + 1][0], a3 = PH[2 * jt + 1][1];
#pragma unroll
            for (int nt2 = 0; nt2 < 8; nt2++) {
                uint2 vf = Vp[(nt2 * 8 + g) * PV64 + jt * 4 + q];
                mma_bf16(OC[nt2], a0, a1, a2, a3, vf.x, vf.y);
            }
        }
    }

    // ---- final row-sum reduction ----
    rl0 += __shfl_xor_sync(0xffffffffu, rl0, 1);
    rl0 += __shfl_xor_sync(0xffffffffu, rl0, 2);
    rl1 += __shfl_xor_sync(0xffffffffu, rl1, 1);
    rl1 += __shfl_xor_sync(0xffffffffu, rl1, 2);

    // ---- normalize + write ----
    {
        float inv0 = 1.f / rl0, inv1 = 1.f / rl1;
        float* ob = g_attn + (size_t)b * C * NSP + n0 + i0 + g;
#pragma unroll
        for (int nt2 = 0; nt2 < 8; nt2++) {
            int d0 = nt2 * 8 + 2 * q;
            ob[(size_t)d0 * NSP]           = OC[nt2][0] * inv0;
            ob[(size_t)(d0 + 1) * NSP]     = OC[nt2][1] * inv0;
            ob[(size_t)d0 * NSP + 8]       = OC[nt2][2] * inv1;
            ob[(size_t)(d0 + 1) * NSP + 8] = OC[nt2][3] * inv1;
        }
    }
    #undef ISSUE_CHUNK
}

// ---------------------------------------------------------------------------
// fused tail (R14 verbatim)
// ---------------------------------------------------------------------------
#define WSP 68
#define UPR 72
#define UPC 152
__global__ __launch_bounds__(256) void tail_kernel(
    const float* __restrict__ w2,
    const float* __restrict__ g2, const float* __restrict__ b2,
    const float* __restrict__ m2, const float* __restrict__ v2,
    const float* __restrict__ w3,
    const float* __restrict__ g3, const float* __restrict__ b3,
    const float* __restrict__ m3, const float* __restrict__ v3,
    const float* __restrict__ x, float* __restrict__ out)
{
    extern __shared__ float smem_f[];
    float* ws = smem_f;
    float* Us = ws + C * WSP;
    float* s_inv = Us + C * UPC;
    float* s_shift = s_inv + C;

    int tid = threadIdx.x;
    int lane = tid & 31;
    int wid = tid >> 5;
    int y0 = blockIdx.x * 2;
    int b = blockIdx.y;

    for (int i = tid; i < C * C; i += 256) {
        int r = i >> 6, c = i & 63;
        ws[r * WSP + c] = __uint_as_float(f2tf32(w3[i]));
    }
    if (tid < C) {
        float inv = g3[tid] * rsqrtf(v3[tid] + EPSBN);
        s_inv[tid] = inv;
        s_shift[tid] = b3[tid] - m3[tid] * inv;
    }

    {
        int xx = lane * 2;
#pragma unroll
        for (int p = 0; p < 8; p++) {
            int c = wid * 8 + p;
            const float* ip = g_attn + ((size_t)(b * 64 + c) << 12);
            float lf[4], m0[4], m1[4], rg[4];
#pragma unroll
            for (int i = 0; i < 4; i++) {
                int yy = y0 - 1 + i;
                if (yy >= 0 && yy < HW) {
                    const float* rp = ip + yy * HW + xx;
                    float2 mid = *(const float2*)rp;
                    lf[i] = (xx > 0) ? rp[-1] : 0.f;
                    m0[i] = mid.x; m1[i] = mid.y;
                    rg[i] = (xx + 2 < HW) ? rp[2] : 0.f;
                } else {
                    lf[i] = m0[i] = m1[i] = rg[i] = 0.f;
                }
            }
            float inv = g2[c] * rsqrtf(v2[c] + EPSBN);
            float sh = b2[c] - m2[c] * inv;
#pragma unroll
            for (int r = 0; r < 2; r++) {
                float a0 = 0.f, a1 = 0.f;
#pragma unroll
                for (int dy = 0; dy < 3; dy++) {
                    int i = r + dy;
                    float c0 = w2[c * 9 + dy * 3 + 0];
                    float c1 = w2[c * 9 + dy * 3 + 1];
                    float c2 = w2[c * 9 + dy * 3 + 2];
                    a0 += c0 * lf[i] + c1 * m0[i] + c2 * m1[i];
                    a1 += c0 * m0[i] + c1 * m1[i] + c2 * rg[i];
                }
                float u0 = fmaxf(a0 * inv + sh, 0.f);
                float u1 = fmaxf(a1 * inv + sh, 0.f);
                Us[c * UPC + r * UPR + xx]     = __uint_as_float(f2tf32(u0));
                Us[c * UPC + r * UPR + xx + 1] = __uint_as_float(f2tf32(u1));
            }
        }
    }
    __syncthreads();

    {
        const int g = lane >> 2, q = lane & 3;
#pragma unroll
        for (int r = 0; r < 2; r++) {
            const float* Ur = Us + r * UPR;
            float OC3[4][4];
#pragma unroll
            for (int mt = 0; mt < 4; mt++)
                OC3[mt][0] = OC3[mt][1] = OC3[mt][2] = OC3[mt][3] = 0.f;
#pragma unroll
            for (int ks = 0; ks < 8; ks++) {
                unsigned b0 = __float_as_uint(Ur[(ks * 8 + q) * UPC + wid * 8 + g]);
                unsigned b1 = __float_as_uint(Ur[(ks * 8 + q + 4) * UPC + wid * 8 + g]);
#pragma unroll
                for (int mt = 0; mt < 4; mt++) {
                    unsigned a0 = __float_as_uint(ws[(mt * 16 + g) * WSP + ks * 8 + q]);
                    unsigned a1 = __float_as_uint(ws[(mt * 16 + g + 8) * WSP + ks * 8 + q]);
                    unsigned a2 = __float_as_uint(ws[(mt * 16 + g) * WSP + ks * 8 + q + 4]);
                    unsigned a3 = __float_as_uint(ws[(mt * 16 + g + 8) * WSP + ks * 8 + q + 4]);
                    mma_tf32(OC3[mt], a0, a1, a2, a3, b0, b1);
                }
            }
            int n = (y0 + r) * HW + wid * 8 + 2 * q;
            const float* xp = x + (size_t)b * C * NSP + n;
            float* op = out + (size_t)b * C * NSP + n;
#pragma unroll
            for (int mt = 0; mt < 4; mt++) {
                int o0 = mt * 16 + g;
                float i0v = s_inv[o0], sh0 = s_shift[o0];
                float i1v = s_inv[o0 + 8], sh1 = s_shift[o0 + 8];
                op[(size_t)o0 * NSP]           = OC3[mt][0] * i0v + sh0 + xp[(size_t)o0 * NSP];
                op[(size_t)o0 * NSP + 1]       = OC3[mt][1] * i0v + sh0 + xp[(size_t)o0 * NSP + 1];
                op[(size_t)(o0 + 8) * NSP]     = OC3[mt][2] * i1v + sh1 + xp[(size_t)(o0 + 8) * NSP];
                op[(size_t)(o0 + 8) * NSP + 1] = OC3[mt][3] * i1v + sh1 + xp[(size_t)(o0 + 8) * NSP + 1];
            }
        }
    }
}

// ---------------------------------------------------------------------------
extern "C" void kernel_launch(void* const* d_in, const int* in_sizes, int n_in,
                              void* d_out, int out_size)
{
    const float* x    = (const float*)d_in[0];
    const float* w1   = (const float*)d_in[1];
    const float* bn1g = (const float*)d_in[2];
    const float* bn1b = (const float*)d_in[3];
    const float* bn1m = (const float*)d_in[4];
    const float* bn1v = (const float*)d_in[5];
    const float* w2   = (const float*)d_in[6];
    const float* bn2g = (const float*)d_in[7];
    const float* bn2b = (const float*)d_in[8];
    const float* bn2m = (const float*)d_in[9];
    const float* bn2v = (const float*)d_in[10];
    const float* w3   = (const float*)d_in[11];
    const float* bn3g = (const float*)d_in[12];
    const float* bn3b = (const float*)d_in[13];
    const float* bn3m = (const float*)d_in[14];
    const float* bn3v = (const float*)d_in[15];
    float* out = (float*)d_out;

    const int tail_smem = (C * WSP + C * UPC + 2 * C) * 4;
    cudaFuncSetAttribute(tail_kernel,
                         cudaFuncAttributeMaxDynamicSharedMemorySize, tail_smem);

    conv1_mma_kernel<<<dim3(NSP / 128, BB), 256>>>(x, w1, bn1g, bn1b, bn1m, bn1v);
    attn_mma_kernel<<<dim3(NSP / TNQ, BB), 256>>>(x);
    tail_kernel<<<dim3(HW / 2, BB), 256, tail_smem>>>(w2, bn2g, bn2b, bn2m, bn2v,
                                                      w3, bn3g, bn3b, bn3m, bn3v, x, out);
}